// round 3
// baseline (speedup 1.0000x reference)
#include <cuda_runtime.h>

// ---------------------------------------------------------------------------
// InstanceModelClassic: rigid-transform trilinear resampling of a 256^3 volume
//
// Inputs (metadata order):
//   d_in[0] image_targ  float32 [1,1,256,256,256]
//   d_in[1] rotation    float32 [1,3]
//   d_in[2] translation float32 [1,3]
//   d_in[3] ref_v2r     float32 [4,4]
//   d_in[4] flo_v2r     float32 [4,4]
// Output: float32 [1,1,256,256,256]
// ---------------------------------------------------------------------------

__device__ float g_T[12];   // 3x4 rows of composed voxel->voxel transform

__device__ static void mat4_inv(const float* A, float* Ainv) {
    float M[4][8];
    for (int r = 0; r < 4; r++) {
        for (int c = 0; c < 4; c++) {
            M[r][c] = A[r * 4 + c];
            M[r][4 + c] = (r == c) ? 1.0f : 0.0f;
        }
    }
    for (int col = 0; col < 4; col++) {
        int piv = col;
        float best = fabsf(M[col][col]);
        for (int r = col + 1; r < 4; r++) {
            float v = fabsf(M[r][col]);
            if (v > best) { best = v; piv = r; }
        }
        if (piv != col)
            for (int c = 0; c < 8; c++) {
                float t = M[col][c]; M[col][c] = M[piv][c]; M[piv][c] = t;
            }
        float inv_p = 1.0f / M[col][col];
        for (int c = 0; c < 8; c++) M[col][c] *= inv_p;
        for (int r = 0; r < 4; r++) {
            if (r == col) continue;
            float f = M[r][col];
            if (f != 0.0f)
                for (int c = 0; c < 8; c++) M[r][c] -= f * M[col][c];
        }
    }
    for (int r = 0; r < 4; r++)
        for (int c = 0; c < 4; c++)
            Ainv[r * 4 + c] = M[r][4 + c];
}

__device__ static void mm4(const float* A, const float* B, float* C) {
    for (int r = 0; r < 4; r++)
        for (int c = 0; c < 4; c++) {
            float s = 0.0f;
            for (int k = 0; k < 4; k++) s += A[r * 4 + k] * B[k * 4 + c];
            C[r * 4 + c] = s;
        }
}

__global__ void setup_transform_kernel(const float* __restrict__ rotation,
                                       const float* __restrict__ translation,
                                       const float* __restrict__ ref_v2r,
                                       const float* __restrict__ flo_v2r) {
    float cx = cosf(rotation[0]), cy = cosf(rotation[1]), cz = cosf(rotation[2]);
    float sx = sinf(rotation[0]), sy = sinf(rotation[1]), sz = sinf(rotation[2]);

    float Rx[9] = {1, 0, 0,   0, cx, -sx,   0, sx, cx};
    float Ry[9] = {cy, 0, sy, 0, 1, 0,      -sy, 0, cy};
    float Rz[9] = {cz, -sz, 0, sz, cz, 0,   0, 0, 1};
    float Ryz[9], R[9];
    for (int r = 0; r < 3; r++)
        for (int c = 0; c < 3; c++) {
            float s = 0.0f;
            for (int k = 0; k < 3; k++) s += Ry[r * 3 + k] * Rz[k * 3 + c];
            Ryz[r * 3 + c] = s;
        }
    for (int r = 0; r < 3; r++)
        for (int c = 0; c < 3; c++) {
            float s = 0.0f;
            for (int k = 0; k < 3; k++) s += Rx[r * 3 + k] * Ryz[k * 3 + c];
            R[r * 3 + c] = s;
        }

    float Trig[16];
    for (int r = 0; r < 3; r++) {
        for (int c = 0; c < 3; c++) Trig[r * 4 + c] = R[r * 3 + c];
        Trig[r * 4 + 3] = translation[r];
    }
    Trig[12] = 0.0f; Trig[13] = 0.0f; Trig[14] = 0.0f; Trig[15] = 1.0f;

    float Finv[16], tmp[16], T[16];
    mat4_inv(flo_v2r, Finv);
    mm4(Trig, ref_v2r, tmp);
    mm4(Finv, tmp, T);

    for (int i = 0; i < 12; i++) g_T[i] = T[i];
}

// ----------------------------------------------------------------------------
// Tiled resample kernel.
//   Output tile per block: TI x TJ x TK = 16 x 16 x 64 voxels.
//   Input staged in smem: SMX x SMY x SMZ = 28 x 28 x 72 (pitched), 225792 B.
//   1024 threads: 64 k-lanes x 16 row-groups; 16 (i,j) rows per thread.
// ----------------------------------------------------------------------------
constexpr int TI = 16, TJ = 16, TK = 64;
constexpr int SMX = 28, SMY = 28, SMZ = 72;
constexpr int SM_ELEMS = SMX * SMY * SMZ;          // 56448
constexpr int SM_BYTES = SM_ELEMS * 4;             // 225792
constexpr int NTHREADS = 1024;

// min/max helpers over a coordinate range [lo, lo+len-1] for coefficient t
__device__ __forceinline__ float axis_min(float t, int lo, int len) {
    return (t >= 0.0f) ? t * (float)lo : t * (float)(lo + len - 1);
}
__device__ __forceinline__ float axis_max(float t, int lo, int len) {
    return (t >= 0.0f) ? t * (float)(lo + len - 1) : t * (float)lo;
}

__global__ void __launch_bounds__(NTHREADS, 1)
tiled_trilinear_kernel(const float* __restrict__ img, float* __restrict__ out) {
    extern __shared__ float tile[];

    const int bid = blockIdx.x;
    const int k0 = (bid & 3) << 6;          // 4 k-tiles of 64
    const int j0 = ((bid >> 2) & 15) << 4;  // 16 j-tiles of 16
    const int i0 = (bid >> 6) << 4;         // 16 i-tiles of 16

    const float T00 = g_T[0], T01 = g_T[1],  T02 = g_T[2],  T03 = g_T[3];
    const float T10 = g_T[4], T11 = g_T[5],  T12 = g_T[6],  T13 = g_T[7];
    const float T20 = g_T[8], T21 = g_T[9],  T22 = g_T[10], T23 = g_T[11];

    // Input bbox of this output tile (computed redundantly by every thread;
    // identical results -> block-uniform branch below).
    const float mnI = T03 + axis_min(T00, i0, TI) + axis_min(T01, j0, TJ) + axis_min(T02, k0, TK);
    const float mxI = T03 + axis_max(T00, i0, TI) + axis_max(T01, j0, TJ) + axis_max(T02, k0, TK);
    const float mnJ = T13 + axis_min(T10, i0, TI) + axis_min(T11, j0, TJ) + axis_min(T12, k0, TK);
    const float mxJ = T13 + axis_max(T10, i0, TI) + axis_max(T11, j0, TJ) + axis_max(T12, k0, TK);
    const float mnK = T23 + axis_min(T20, i0, TI) + axis_min(T21, j0, TJ) + axis_min(T22, k0, TK);
    const float mxK = T23 + axis_max(T20, i0, TI) + axis_max(T21, j0, TJ) + axis_max(T22, k0, TK);

    int loX = max((int)floorf(mnI), 0);
    int hiX = min((int)floorf(mxI) + 1, 255);
    int loY = max((int)floorf(mnJ), 0);
    int hiY = min((int)floorf(mxJ) + 1, 255);
    int loZ = max((int)floorf(mnK), 0);
    int hiZ = min((int)floorf(mxK) + 1, 255);

    const bool fits = (hiX - loX < SMX) && (hiY - loY < SMY) && (hiZ - loZ < SMZ);

    const int tid = threadIdx.x;
    const int tx = tid & 63;     // k lane
    const int tg = tid >> 6;     // row group (16 groups)

    if (fits) {
        // ---- stage input region into pitched smem tile ----
        // full padded region with clamped source coords (simple + coalesced)
        for (int idx = tid; idx < SM_ELEMS; idx += NTHREADS) {
            const int xp = idx / (SMY * SMZ);
            const int rem = idx - xp * (SMY * SMZ);
            const int yp = rem / SMZ;
            const int zp = rem - yp * SMZ;
            const int xg = min(loX + xp, 255);
            const int yg = min(loY + yp, 255);
            const int zg = min(loZ + zp, 255);
            tile[idx] = __ldg(img + ((xg << 16) | (yg << 8) | zg));
        }
        __syncthreads();

        const int k = k0 + tx;
        const float fk = (float)k;

#pragma unroll 4
        for (int r = tg; r < TI * TJ; r += 16) {
            const int i = i0 + (r >> 4);
            const int j = j0 + (r & 15);
            const float fi = (float)i, fj = (float)j;

            const float II = fmaf(T00, fi, fmaf(T01, fj, fmaf(T02, fk, T03)));
            const float JJ = fmaf(T10, fi, fmaf(T11, fj, fmaf(T12, fk, T13)));
            const float KK = fmaf(T20, fi, fmaf(T21, fj, fmaf(T22, fk, T23)));

            const bool ok = (II > 0.0f) & (JJ > 0.0f) & (KK > 0.0f) &
                            (II <= 255.0f) & (JJ <= 255.0f) & (KK <= 255.0f);

            float v = 0.0f;
            if (ok) {
                const int x0 = __float2int_rd(II);
                const int y0 = __float2int_rd(JJ);
                const int z0 = __float2int_rd(KK);
                const float wcx = II - (float)x0, wfx = 1.0f - wcx;
                const float wcy = JJ - (float)y0, wfy = 1.0f - wcy;
                const float wcz = KK - (float)z0, wfz = 1.0f - wcz;

                const int ox = (x0 < 255) ? (SMY * SMZ) : 0;
                const int oy = (y0 < 255) ? SMZ : 0;
                const int oz = (z0 < 255) ? 1 : 0;

                const int base = (x0 - loX) * (SMY * SMZ) + (y0 - loY) * SMZ + (z0 - loZ);
                const float* p00 = tile + base;
                const float* p01 = p00 + oy;
                const float* p10 = p00 + ox;
                const float* p11 = p10 + oy;

                const float v000 = p00[0],  v001 = p00[oz];
                const float v010 = p01[0],  v011 = p01[oz];
                const float v100 = p10[0],  v101 = p10[oz];
                const float v110 = p11[0],  v111 = p11[oz];

                // exact reference summation structure
                v = v000 * (wfx * wfy * wfz) +
                    v001 * (wfx * wfy * wcz) +
                    v010 * (wfx * wcy * wfz) +
                    v011 * (wfx * wcy * wcz) +
                    v100 * (wcx * wfy * wfz) +
                    v101 * (wcx * wfy * wcz) +
                    v110 * (wcx * wcy * wfz) +
                    v111 * (wcx * wcy * wcz);
            }
            out[((i << 8) | j) << 8 | k] = v;
        }
    } else {
        // ---- fallback: direct global gather (large rotations) ----
        const int k = k0 + tx;
        const float fk = (float)k;
        for (int r = tg; r < TI * TJ; r += 16) {
            const int i = i0 + (r >> 4);
            const int j = j0 + (r & 15);
            const float fi = (float)i, fj = (float)j;

            const float II = fmaf(T00, fi, fmaf(T01, fj, fmaf(T02, fk, T03)));
            const float JJ = fmaf(T10, fi, fmaf(T11, fj, fmaf(T12, fk, T13)));
            const float KK = fmaf(T20, fi, fmaf(T21, fj, fmaf(T22, fk, T23)));

            const bool ok = (II > 0.0f) & (JJ > 0.0f) & (KK > 0.0f) &
                            (II <= 255.0f) & (JJ <= 255.0f) & (KK <= 255.0f);

            float v = 0.0f;
            if (ok) {
                const int x0 = __float2int_rd(II);
                const int y0 = __float2int_rd(JJ);
                const int z0 = __float2int_rd(KK);
                const float wcx = II - (float)x0, wfx = 1.0f - wcx;
                const float wcy = JJ - (float)y0, wfy = 1.0f - wcy;
                const float wcz = KK - (float)z0, wfz = 1.0f - wcz;

                const int ox = (x0 < 255) ? 65536 : 0;
                const int oy = (y0 < 255) ? 256 : 0;
                const int oz = (z0 < 255) ? 1 : 0;

                const int base = (x0 << 16) | (y0 << 8) | z0;
                const float* p00 = img + base;
                const float* p01 = p00 + oy;
                const float* p10 = p00 + ox;
                const float* p11 = p10 + oy;

                const float v000 = __ldg(p00),      v001 = __ldg(p00 + oz);
                const float v010 = __ldg(p01),      v011 = __ldg(p01 + oz);
                const float v100 = __ldg(p10),      v101 = __ldg(p10 + oz);
                const float v110 = __ldg(p11),      v111 = __ldg(p11 + oz);

                v = v000 * (wfx * wfy * wfz) +
                    v001 * (wfx * wfy * wcz) +
                    v010 * (wfx * wcy * wfz) +
                    v011 * (wfx * wcy * wcz) +
                    v100 * (wcx * wfy * wfz) +
                    v101 * (wcx * wfy * wcz) +
                    v110 * (wcx * wcy * wfz) +
                    v111 * (wcx * wcy * wcz);
            }
            out[((i << 8) | j) << 8 | k] = v;
        }
    }
}

extern "C" void kernel_launch(void* const* d_in, const int* in_sizes, int n_in,
                              void* d_out, int out_size) {
    const float* img         = (const float*)d_in[0];
    const float* rotation    = (const float*)d_in[1];
    const float* translation = (const float*)d_in[2];
    const float* ref_v2r     = (const float*)d_in[3];
    const float* flo_v2r     = (const float*)d_in[4];
    float* out = (float*)d_out;

    setup_transform_kernel<<<1, 1>>>(rotation, translation, ref_v2r, flo_v2r);

    static bool attr_set = false;
    if (!attr_set) {
        cudaFuncSetAttribute(tiled_trilinear_kernel,
                             cudaFuncAttributeMaxDynamicSharedMemorySize, SM_BYTES);
        attr_set = true;
    }

    tiled_trilinear_kernel<<<1024, NTHREADS, SM_BYTES>>>(img, out);
}

// round 4
// speedup vs baseline: 1.2718x; 1.2718x over previous
#include <cuda_runtime.h>

// ---------------------------------------------------------------------------
// InstanceModelClassic: rigid-transform trilinear resampling of a 256^3 volume
// ---------------------------------------------------------------------------

__device__ float g_T[12];   // 3x4 rows of composed voxel->voxel transform

__device__ static void mat4_inv(const float* A, float* Ainv) {
    float M[4][8];
    for (int r = 0; r < 4; r++) {
        for (int c = 0; c < 4; c++) {
            M[r][c] = A[r * 4 + c];
            M[r][4 + c] = (r == c) ? 1.0f : 0.0f;
        }
    }
    for (int col = 0; col < 4; col++) {
        int piv = col;
        float best = fabsf(M[col][col]);
        for (int r = col + 1; r < 4; r++) {
            float v = fabsf(M[r][col]);
            if (v > best) { best = v; piv = r; }
        }
        if (piv != col)
            for (int c = 0; c < 8; c++) {
                float t = M[col][c]; M[col][c] = M[piv][c]; M[piv][c] = t;
            }
        float inv_p = 1.0f / M[col][col];
        for (int c = 0; c < 8; c++) M[col][c] *= inv_p;
        for (int r = 0; r < 4; r++) {
            if (r == col) continue;
            float f = M[r][col];
            if (f != 0.0f)
                for (int c = 0; c < 8; c++) M[r][c] -= f * M[col][c];
        }
    }
    for (int r = 0; r < 4; r++)
        for (int c = 0; c < 4; c++)
            Ainv[r * 4 + c] = M[r][4 + c];
}

__device__ static void mm4(const float* A, const float* B, float* C) {
    for (int r = 0; r < 4; r++)
        for (int c = 0; c < 4; c++) {
            float s = 0.0f;
            for (int k = 0; k < 4; k++) s += A[r * 4 + k] * B[k * 4 + c];
            C[r * 4 + c] = s;
        }
}

__global__ void setup_transform_kernel(const float* __restrict__ rotation,
                                       const float* __restrict__ translation,
                                       const float* __restrict__ ref_v2r,
                                       const float* __restrict__ flo_v2r) {
    float cx = cosf(rotation[0]), cy = cosf(rotation[1]), cz = cosf(rotation[2]);
    float sx = sinf(rotation[0]), sy = sinf(rotation[1]), sz = sinf(rotation[2]);

    float Rx[9] = {1, 0, 0,   0, cx, -sx,   0, sx, cx};
    float Ry[9] = {cy, 0, sy, 0, 1, 0,      -sy, 0, cy};
    float Rz[9] = {cz, -sz, 0, sz, cz, 0,   0, 0, 1};
    float Ryz[9], R[9];
    for (int r = 0; r < 3; r++)
        for (int c = 0; c < 3; c++) {
            float s = 0.0f;
            for (int k = 0; k < 3; k++) s += Ry[r * 3 + k] * Rz[k * 3 + c];
            Ryz[r * 3 + c] = s;
        }
    for (int r = 0; r < 3; r++)
        for (int c = 0; c < 3; c++) {
            float s = 0.0f;
            for (int k = 0; k < 3; k++) s += Rx[r * 3 + k] * Ryz[k * 3 + c];
            R[r * 3 + c] = s;
        }

    float Trig[16];
    for (int r = 0; r < 3; r++) {
        for (int c = 0; c < 3; c++) Trig[r * 4 + c] = R[r * 3 + c];
        Trig[r * 4 + 3] = translation[r];
    }
    Trig[12] = 0.0f; Trig[13] = 0.0f; Trig[14] = 0.0f; Trig[15] = 1.0f;

    float Finv[16], tmp[16], T[16];
    mat4_inv(flo_v2r, Finv);
    mm4(Trig, ref_v2r, tmp);
    mm4(Finv, tmp, T);

    for (int i = 0; i < 12; i++) g_T[i] = T[i];
}

// ----------------------------------------------------------------------------
// Tiled resample kernel.
//   Output tile: TI x TJ x TK = 16 x 16 x 32  (8192 voxels, 2048 blocks)
//   Input staged: SMX x SMY x SMZ = 22 x 22 x 40 floats = 77440 B -> 2 CTA/SM
//   512 threads: 32 k-lanes x 16 j-rows; 16 i-planes per thread.
// ----------------------------------------------------------------------------
constexpr int TI = 16, TJ = 16, TK = 32;
constexpr int SMX = 22, SMY = 22, SMZ = 40;
constexpr int SM_ELEMS = SMX * SMY * SMZ;        // 19360
constexpr int SM_BYTES = SM_ELEMS * 4;           // 77440
constexpr int NTHREADS = 512;
constexpr int PXY = SMY * SMZ;                   // 880  (x pitch, floats)
// tap offsets in floats
constexpr int OY = SMZ;        // 40
constexpr int OX = PXY;        // 880

__device__ __forceinline__ float axis_min(float t, int lo, int len) {
    return (t >= 0.0f) ? t * (float)lo : t * (float)(lo + len - 1);
}
__device__ __forceinline__ float axis_max(float t, int lo, int len) {
    return (t >= 0.0f) ? t * (float)(lo + len - 1) : t * (float)lo;
}

__global__ void __launch_bounds__(NTHREADS, 2)
tiled_trilinear_kernel(const float* __restrict__ img, float* __restrict__ out) {
    __shared__ float tile[SM_ELEMS];

    const int bid = blockIdx.x;
    const int k0 = (bid & 7) << 5;           // 8 k-tiles of 32
    const int j0 = ((bid >> 3) & 15) << 4;   // 16 j-tiles of 16
    const int i0 = (bid >> 7) << 4;          // 16 i-tiles of 16

    const float T00 = g_T[0], T01 = g_T[1],  T02 = g_T[2],  T03 = g_T[3];
    const float T10 = g_T[4], T11 = g_T[5],  T12 = g_T[6],  T13 = g_T[7];
    const float T20 = g_T[8], T21 = g_T[9],  T22 = g_T[10], T23 = g_T[11];

    // Input-space bbox of this output tile (block-uniform).
    const float mnI = T03 + axis_min(T00, i0, TI) + axis_min(T01, j0, TJ) + axis_min(T02, k0, TK);
    const float mxI = T03 + axis_max(T00, i0, TI) + axis_max(T01, j0, TJ) + axis_max(T02, k0, TK);
    const float mnJ = T13 + axis_min(T10, i0, TI) + axis_min(T11, j0, TJ) + axis_min(T12, k0, TK);
    const float mxJ = T13 + axis_max(T10, i0, TI) + axis_max(T11, j0, TJ) + axis_max(T12, k0, TK);
    const float mnK = T23 + axis_min(T20, i0, TI) + axis_min(T21, j0, TJ) + axis_min(T22, k0, TK);
    const float mxK = T23 + axis_max(T20, i0, TI) + axis_max(T21, j0, TJ) + axis_max(T22, k0, TK);

    const int loX  = max(__float2int_rd(mnI), 0);
    const int loY  = max(__float2int_rd(mnJ), 0);
    const int loZ  = max(__float2int_rd(mnK), 0);
    const int zloA = loZ & ~3;                       // 16B-aligned z origin
    const int hiX  = min(__float2int_rd(mxI) + 1, 255);
    const int hiY  = min(__float2int_rd(mxJ) + 1, 255);
    const int hiZ  = min(__float2int_rd(mxK) + 1, 255);

    const bool fits = (hiX - loX < SMX) && (hiY - loY < SMY) && (hiZ - zloA < SMZ);

    const int tid = threadIdx.x;
    const int kl = tid & 31;        // k lane (warp-contiguous)
    const int tg = tid >> 5;        // j row within tile
    const int k = k0 + kl;
    const int j = j0 + tg;
    const float fk = (float)k, fj = (float)j;

    // per-thread (j,k)-dependent bases: II = fmaf(T00, fi, IIb)
    const float IIb = fmaf(T01, fj, fmaf(T02, fk, T03));
    const float JJb = fmaf(T11, fj, fmaf(T12, fk, T13));
    const float KKb = fmaf(T21, fj, fmaf(T22, fk, T23));

    float* outp = out + (((i0 << 8) | j) << 8 | k);

    if (fits) {
        // ------------------- stage input region into smem -------------------
        if (zloA + SMZ <= 256) {
            // fully in-range z: vectorized float4 staging
            constexpr int NQ = SMZ / 4;                 // 10
            constexpr int N4 = SMX * SMY * NQ;          // 4840
            for (int idx = tid; idx < N4; idx += NTHREADS) {
                const int xp = idx / (SMY * NQ);
                const int rem = idx - xp * (SMY * NQ);
                const int yp = rem / NQ;
                const int q = rem - yp * NQ;
                const int xg = min(loX + xp, 255);
                const int yg = min(loY + yp, 255);
                const float4 val = *reinterpret_cast<const float4*>(
                    img + ((xg << 16) | (yg << 8)) + zloA + (q << 2));
                *reinterpret_cast<float4*>(&tile[(xp * SMY + yp) * SMZ + (q << 2)]) = val;
            }
        } else {
            // z clamp needed near the high boundary: scalar staging
            for (int idx = tid; idx < SM_ELEMS; idx += NTHREADS) {
                const int xp = idx / PXY;
                const int rem = idx - xp * PXY;
                const int yp = rem / SMZ;
                const int zp = rem - yp * SMZ;
                const int xg = min(loX + xp, 255);
                const int yg = min(loY + yp, 255);
                const int zg = min(zloA + zp, 255);
                tile[idx] = __ldg(img + ((xg << 16) | (yg << 8) | zg));
            }
        }
        __syncthreads();

        // tile-space offset: base = x0*880 + y0*40 + z0 + Coff
        const int Coff = -(loX * PXY + loY * SMZ + zloA);
        const float* tilep = tile;

        // block-uniform interior test (all voxels strictly inside volume)
        const bool interior = (mnI > 0.01f) && (mxI < 254.99f) &&
                              (mnJ > 0.01f) && (mxJ < 254.99f) &&
                              (mnK > 0.01f) && (mxK < 254.99f);

        if (interior) {
            float fi = (float)i0;
#pragma unroll
            for (int e = 0; e < TI; e++) {
                const float II = fmaf(T00, fi, IIb);
                const float JJ = fmaf(T10, fi, JJb);
                const float KK = fmaf(T20, fi, KKb);
                fi += 1.0f;

                const float fx = floorf(II);
                const float fy = floorf(JJ);
                const float fz = floorf(KK);
                const float wcx = II - fx, wfx = 1.0f - wcx;
                const float wcy = JJ - fy, wfy = 1.0f - wcy;
                const float wcz = KK - fz, wfz = 1.0f - wcz;

                // linear smem index computed in float (exact below 2^24)
                const int base = __float2int_rn(
                    fmaf(fx, (float)PXY, fmaf(fy, (float)SMZ, fz))) + Coff;
                const float* p = tilep + base;

                const float v000 = p[0],        v001 = p[1];
                const float v010 = p[OY],       v011 = p[OY + 1];
                const float v100 = p[OX],       v101 = p[OX + 1];
                const float v110 = p[OX + OY],  v111 = p[OX + OY + 1];

                const float a00 = wfx * wfy, a01 = wfx * wcy;
                const float a10 = wcx * wfy, a11 = wcx * wcy;
                float v;
                v =      v000 * (a00 * wfz);
                v = fmaf(v001,  a00 * wcz, v);
                v = fmaf(v010,  a01 * wfz, v);
                v = fmaf(v011,  a01 * wcz, v);
                v = fmaf(v100,  a10 * wfz, v);
                v = fmaf(v101,  a10 * wcz, v);
                v = fmaf(v110,  a11 * wfz, v);
                v = fmaf(v111,  a11 * wcz, v);

                outp[e << 16] = v;
            }
        } else {
            // boundary tile: per-voxel mask + clamped +1 offsets
            float fi = (float)i0;
#pragma unroll 4
            for (int e = 0; e < TI; e++) {
                const float II = fmaf(T00, fi, IIb);
                const float JJ = fmaf(T10, fi, JJb);
                const float KK = fmaf(T20, fi, KKb);
                fi += 1.0f;

                const bool ok = (II > 0.0f) & (JJ > 0.0f) & (KK > 0.0f) &
                                (II <= 255.0f) & (JJ <= 255.0f) & (KK <= 255.0f);
                float v = 0.0f;
                if (ok) {
                    const int x0 = __float2int_rd(II);
                    const int y0 = __float2int_rd(JJ);
                    const int z0 = __float2int_rd(KK);
                    const float wcx = II - (float)x0, wfx = 1.0f - wcx;
                    const float wcy = JJ - (float)y0, wfy = 1.0f - wcy;
                    const float wcz = KK - (float)z0, wfz = 1.0f - wcz;

                    const int ox = (x0 < 255) ? OX : 0;
                    const int oy = (y0 < 255) ? OY : 0;
                    const int oz = (z0 < 255) ? 1 : 0;

                    const int base = x0 * PXY + y0 * SMZ + z0 + Coff;
                    const float* p = tilep + base;

                    const float v000 = p[0],        v001 = p[oz];
                    const float v010 = p[oy],       v011 = p[oy + oz];
                    const float v100 = p[ox],       v101 = p[ox + oz];
                    const float v110 = p[ox + oy],  v111 = p[ox + oy + oz];

                    const float a00 = wfx * wfy, a01 = wfx * wcy;
                    const float a10 = wcx * wfy, a11 = wcx * wcy;
                    v =      v000 * (a00 * wfz);
                    v = fmaf(v001,  a00 * wcz, v);
                    v = fmaf(v010,  a01 * wfz, v);
                    v = fmaf(v011,  a01 * wcz, v);
                    v = fmaf(v100,  a10 * wfz, v);
                    v = fmaf(v101,  a10 * wcz, v);
                    v = fmaf(v110,  a11 * wfz, v);
                    v = fmaf(v111,  a11 * wcz, v);
                }
                outp[e << 16] = v;
            }
        }
    } else {
        // ---------------- fallback: direct global gather ----------------
        float fi = (float)i0;
        for (int e = 0; e < TI; e++) {
            const float II = fmaf(T00, fi, IIb);
            const float JJ = fmaf(T10, fi, JJb);
            const float KK = fmaf(T20, fi, KKb);
            fi += 1.0f;

            const bool ok = (II > 0.0f) & (JJ > 0.0f) & (KK > 0.0f) &
                            (II <= 255.0f) & (JJ <= 255.0f) & (KK <= 255.0f);
            float v = 0.0f;
            if (ok) {
                const int x0 = __float2int_rd(II);
                const int y0 = __float2int_rd(JJ);
                const int z0 = __float2int_rd(KK);
                const float wcx = II - (float)x0, wfx = 1.0f - wcx;
                const float wcy = JJ - (float)y0, wfy = 1.0f - wcy;
                const float wcz = KK - (float)z0, wfz = 1.0f - wcz;

                const int ox = (x0 < 255) ? 65536 : 0;
                const int oy = (y0 < 255) ? 256 : 0;
                const int oz = (z0 < 255) ? 1 : 0;

                const float* p = img + ((x0 << 16) | (y0 << 8) | z0);
                const float v000 = __ldg(p),            v001 = __ldg(p + oz);
                const float v010 = __ldg(p + oy),       v011 = __ldg(p + oy + oz);
                const float v100 = __ldg(p + ox),       v101 = __ldg(p + ox + oz);
                const float v110 = __ldg(p + ox + oy),  v111 = __ldg(p + ox + oy + oz);

                const float a00 = wfx * wfy, a01 = wfx * wcy;
                const float a10 = wcx * wfy, a11 = wcx * wcy;
                v =      v000 * (a00 * wfz);
                v = fmaf(v001,  a00 * wcz, v);
                v = fmaf(v010,  a01 * wfz, v);
                v = fmaf(v011,  a01 * wcz, v);
                v = fmaf(v100,  a10 * wfz, v);
                v = fmaf(v101,  a10 * wcz, v);
                v = fmaf(v110,  a11 * wfz, v);
                v = fmaf(v111,  a11 * wcz, v);
            }
            outp[e << 16] = v;
        }
    }
}

extern "C" void kernel_launch(void* const* d_in, const int* in_sizes, int n_in,
                              void* d_out, int out_size) {
    const float* img         = (const float*)d_in[0];
    const float* rotation    = (const float*)d_in[1];
    const float* translation = (const float*)d_in[2];
    const float* ref_v2r     = (const float*)d_in[3];
    const float* flo_v2r     = (const float*)d_in[4];
    float* out = (float*)d_out;

    setup_transform_kernel<<<1, 1>>>(rotation, translation, ref_v2r, flo_v2r);
    tiled_trilinear_kernel<<<2048, NTHREADS>>>(img, out);
}

// round 5
// speedup vs baseline: 1.3864x; 1.0901x over previous
#include <cuda_runtime.h>

// ---------------------------------------------------------------------------
// InstanceModelClassic: rigid-transform trilinear resampling of a 256^3 volume
// ---------------------------------------------------------------------------

__device__ float g_T[12];   // 3x4 rows of composed voxel->voxel transform

__device__ static void mat4_inv(const float* A, float* Ainv) {
    float M[4][8];
    for (int r = 0; r < 4; r++) {
        for (int c = 0; c < 4; c++) {
            M[r][c] = A[r * 4 + c];
            M[r][4 + c] = (r == c) ? 1.0f : 0.0f;
        }
    }
    for (int col = 0; col < 4; col++) {
        int piv = col;
        float best = fabsf(M[col][col]);
        for (int r = col + 1; r < 4; r++) {
            float v = fabsf(M[r][col]);
            if (v > best) { best = v; piv = r; }
        }
        if (piv != col)
            for (int c = 0; c < 8; c++) {
                float t = M[col][c]; M[col][c] = M[piv][c]; M[piv][c] = t;
            }
        float inv_p = 1.0f / M[col][col];
        for (int c = 0; c < 8; c++) M[col][c] *= inv_p;
        for (int r = 0; r < 4; r++) {
            if (r == col) continue;
            float f = M[r][col];
            if (f != 0.0f)
                for (int c = 0; c < 8; c++) M[r][c] -= f * M[col][c];
        }
    }
    for (int r = 0; r < 4; r++)
        for (int c = 0; c < 4; c++)
            Ainv[r * 4 + c] = M[r][4 + c];
}

__device__ static void mm4(const float* A, const float* B, float* C) {
    for (int r = 0; r < 4; r++)
        for (int c = 0; c < 4; c++) {
            float s = 0.0f;
            for (int k = 0; k < 4; k++) s += A[r * 4 + k] * B[k * 4 + c];
            C[r * 4 + c] = s;
        }
}

__global__ void setup_transform_kernel(const float* __restrict__ rotation,
                                       const float* __restrict__ translation,
                                       const float* __restrict__ ref_v2r,
                                       const float* __restrict__ flo_v2r) {
    float cx = cosf(rotation[0]), cy = cosf(rotation[1]), cz = cosf(rotation[2]);
    float sx = sinf(rotation[0]), sy = sinf(rotation[1]), sz = sinf(rotation[2]);

    float Rx[9] = {1, 0, 0,   0, cx, -sx,   0, sx, cx};
    float Ry[9] = {cy, 0, sy, 0, 1, 0,      -sy, 0, cy};
    float Rz[9] = {cz, -sz, 0, sz, cz, 0,   0, 0, 1};
    float Ryz[9], R[9];
    for (int r = 0; r < 3; r++)
        for (int c = 0; c < 3; c++) {
            float s = 0.0f;
            for (int k = 0; k < 3; k++) s += Ry[r * 3 + k] * Rz[k * 3 + c];
            Ryz[r * 3 + c] = s;
        }
    for (int r = 0; r < 3; r++)
        for (int c = 0; c < 3; c++) {
            float s = 0.0f;
            for (int k = 0; k < 3; k++) s += Rx[r * 3 + k] * Ryz[k * 3 + c];
            R[r * 3 + c] = s;
        }

    float Trig[16];
    for (int r = 0; r < 3; r++) {
        for (int c = 0; c < 3; c++) Trig[r * 4 + c] = R[r * 3 + c];
        Trig[r * 4 + 3] = translation[r];
    }
    Trig[12] = 0.0f; Trig[13] = 0.0f; Trig[14] = 0.0f; Trig[15] = 1.0f;

    float Finv[16], tmp[16], T[16];
    mat4_inv(flo_v2r, Finv);
    mm4(Trig, ref_v2r, tmp);
    mm4(Finv, tmp, T);

    for (int i = 0; i < 12; i++) g_T[i] = T[i];
}

// ----------------------------------------------------------------------------
// Tiled resample kernel, occupancy-sized.
//   Output tile: TI x TJ x TK = 8 x 16 x 32  (4096 voxels, 4096 blocks)
//   Input staged: SMX x SMY x SMZ = 15 x 22 x 40 floats = 52800 B -> 4 CTA/SM
//   512 threads: 32 k-lanes x 16 j-rows; 8 i-planes per thread.
// ----------------------------------------------------------------------------
constexpr int TI = 8, TJ = 16, TK = 32;
constexpr int SMX = 15, SMY = 22, SMZ = 40;
constexpr int SM_ELEMS = SMX * SMY * SMZ;        // 13200
constexpr int NTHREADS = 512;
constexpr int PXY = SMY * SMZ;                   // 880 (x pitch, floats)
constexpr int OY = SMZ;                          // 40
constexpr int OX = PXY;                          // 880

__device__ __forceinline__ float axis_min(float t, int lo, int len) {
    return (t >= 0.0f) ? t * (float)lo : t * (float)(lo + len - 1);
}
__device__ __forceinline__ float axis_max(float t, int lo, int len) {
    return (t >= 0.0f) ? t * (float)(lo + len - 1) : t * (float)lo;
}

__global__ void __launch_bounds__(NTHREADS, 4)
tiled_trilinear_kernel(const float* __restrict__ img, float* __restrict__ out) {
    __shared__ float tile[SM_ELEMS];

    const int bid = blockIdx.x;
    const int k0 = (bid & 7) << 5;           // 8 k-tiles of 32
    const int j0 = ((bid >> 3) & 15) << 4;   // 16 j-tiles of 16
    const int i0 = (bid >> 7) << 3;          // 32 i-tiles of 8

    const float T00 = g_T[0], T01 = g_T[1],  T02 = g_T[2],  T03 = g_T[3];
    const float T10 = g_T[4], T11 = g_T[5],  T12 = g_T[6],  T13 = g_T[7];
    const float T20 = g_T[8], T21 = g_T[9],  T22 = g_T[10], T23 = g_T[11];

    // Input-space bbox of this output tile (block-uniform).
    const float mnI = T03 + axis_min(T00, i0, TI) + axis_min(T01, j0, TJ) + axis_min(T02, k0, TK);
    const float mxI = T03 + axis_max(T00, i0, TI) + axis_max(T01, j0, TJ) + axis_max(T02, k0, TK);
    const float mnJ = T13 + axis_min(T10, i0, TI) + axis_min(T11, j0, TJ) + axis_min(T12, k0, TK);
    const float mxJ = T13 + axis_max(T10, i0, TI) + axis_max(T11, j0, TJ) + axis_max(T12, k0, TK);
    const float mnK = T23 + axis_min(T20, i0, TI) + axis_min(T21, j0, TJ) + axis_min(T22, k0, TK);
    const float mxK = T23 + axis_max(T20, i0, TI) + axis_max(T21, j0, TJ) + axis_max(T22, k0, TK);

    const int loX  = max(__float2int_rd(mnI), 0);
    const int loY  = max(__float2int_rd(mnJ), 0);
    const int loZ  = max(__float2int_rd(mnK), 0);
    const int zloA = loZ & ~3;                       // 16B-aligned z origin
    const int hiX  = min(__float2int_rd(mxI) + 1, 255);
    const int hiY  = min(__float2int_rd(mxJ) + 1, 255);
    const int hiZ  = min(__float2int_rd(mxK) + 1, 255);

    const bool fits = (hiX - loX < SMX) && (hiY - loY < SMY) && (hiZ - zloA < SMZ);

    const int tid = threadIdx.x;
    const int kl = tid & 31;        // k lane (warp-contiguous)
    const int tg = tid >> 5;        // j row within tile
    const int k = k0 + kl;
    const int j = j0 + tg;
    const float fk = (float)k, fj = (float)j;

    // per-thread (j,k)-dependent bases: II = fmaf(T00, fi, IIb)
    const float IIb = fmaf(T01, fj, fmaf(T02, fk, T03));
    const float JJb = fmaf(T11, fj, fmaf(T12, fk, T13));
    const float KKb = fmaf(T21, fj, fmaf(T22, fk, T23));

    float* outp = out + (((i0 << 8) | j) << 8 | k);

    if (fits) {
        // ------------------- stage input region into smem -------------------
        if (zloA + SMZ <= 256) {
            // fully in-range z: vectorized float4 staging
            constexpr int NQ = SMZ / 4;                 // 10
            constexpr int N4 = SMX * SMY * NQ;          // 3300
            for (int idx = tid; idx < N4; idx += NTHREADS) {
                const int xp = idx / (SMY * NQ);
                const int rem = idx - xp * (SMY * NQ);
                const int yp = rem / NQ;
                const int q = rem - yp * NQ;
                const int xg = min(loX + xp, 255);
                const int yg = min(loY + yp, 255);
                const float4 val = *reinterpret_cast<const float4*>(
                    img + ((xg << 16) | (yg << 8)) + zloA + (q << 2));
                *reinterpret_cast<float4*>(&tile[(xp * SMY + yp) * SMZ + (q << 2)]) = val;
            }
        } else {
            // z clamp needed near the high boundary: scalar staging
            for (int idx = tid; idx < SM_ELEMS; idx += NTHREADS) {
                const int xp = idx / PXY;
                const int rem = idx - xp * PXY;
                const int yp = rem / SMZ;
                const int zp = rem - yp * SMZ;
                const int xg = min(loX + xp, 255);
                const int yg = min(loY + yp, 255);
                const int zg = min(zloA + zp, 255);
                tile[idx] = __ldg(img + ((xg << 16) | (yg << 8) | zg));
            }
        }
        __syncthreads();

        // tile-space offset: base = x0*880 + y0*40 + z0 + Coff
        const int Coff = -(loX * PXY + loY * SMZ + zloA);
        const float* tilep = tile;

        // block-uniform interior test (all voxels strictly inside volume)
        const bool interior = (mnI > 0.01f) && (mxI < 254.99f) &&
                              (mnJ > 0.01f) && (mxJ < 254.99f) &&
                              (mnK > 0.01f) && (mxK < 254.99f);

        if (interior) {
            float fi = (float)i0;
#pragma unroll
            for (int e = 0; e < TI; e++) {
                const float II = fmaf(T00, fi, IIb);
                const float JJ = fmaf(T10, fi, JJb);
                const float KK = fmaf(T20, fi, KKb);
                fi += 1.0f;

                const float fx = floorf(II);
                const float fy = floorf(JJ);
                const float fz = floorf(KK);
                const float wcx = II - fx, wfx = 1.0f - wcx;
                const float wcy = JJ - fy, wfy = 1.0f - wcy;
                const float wcz = KK - fz, wfz = 1.0f - wcz;

                // linear smem index computed in float (exact below 2^24)
                const int base = __float2int_rn(
                    fmaf(fx, (float)PXY, fmaf(fy, (float)SMZ, fz))) + Coff;
                const float* p = tilep + base;

                const float v000 = p[0],        v001 = p[1];
                const float v010 = p[OY],       v011 = p[OY + 1];
                const float v100 = p[OX],       v101 = p[OX + 1];
                const float v110 = p[OX + OY],  v111 = p[OX + OY + 1];

                const float a00 = wfx * wfy, a01 = wfx * wcy;
                const float a10 = wcx * wfy, a11 = wcx * wcy;
                float v;
                v =      v000 * (a00 * wfz);
                v = fmaf(v001,  a00 * wcz, v);
                v = fmaf(v010,  a01 * wfz, v);
                v = fmaf(v011,  a01 * wcz, v);
                v = fmaf(v100,  a10 * wfz, v);
                v = fmaf(v101,  a10 * wcz, v);
                v = fmaf(v110,  a11 * wfz, v);
                v = fmaf(v111,  a11 * wcz, v);

                outp[e << 16] = v;
            }
        } else {
            // boundary tile: per-voxel mask + clamped +1 offsets
            float fi = (float)i0;
#pragma unroll
            for (int e = 0; e < TI; e++) {
                const float II = fmaf(T00, fi, IIb);
                const float JJ = fmaf(T10, fi, JJb);
                const float KK = fmaf(T20, fi, KKb);
                fi += 1.0f;

                const bool ok = (II > 0.0f) & (JJ > 0.0f) & (KK > 0.0f) &
                                (II <= 255.0f) & (JJ <= 255.0f) & (KK <= 255.0f);
                float v = 0.0f;
                if (ok) {
                    const int x0 = __float2int_rd(II);
                    const int y0 = __float2int_rd(JJ);
                    const int z0 = __float2int_rd(KK);
                    const float wcx = II - (float)x0, wfx = 1.0f - wcx;
                    const float wcy = JJ - (float)y0, wfy = 1.0f - wcy;
                    const float wcz = KK - (float)z0, wfz = 1.0f - wcz;

                    const int ox = (x0 < 255) ? OX : 0;
                    const int oy = (y0 < 255) ? OY : 0;
                    const int oz = (z0 < 255) ? 1 : 0;

                    const int base = x0 * PXY + y0 * SMZ + z0 + Coff;
                    const float* p = tilep + base;

                    const float v000 = p[0],        v001 = p[oz];
                    const float v010 = p[oy],       v011 = p[oy + oz];
                    const float v100 = p[ox],       v101 = p[ox + oz];
                    const float v110 = p[ox + oy],  v111 = p[ox + oy + oz];

                    const float a00 = wfx * wfy, a01 = wfx * wcy;
                    const float a10 = wcx * wfy, a11 = wcx * wcy;
                    v =      v000 * (a00 * wfz);
                    v = fmaf(v001,  a00 * wcz, v);
                    v = fmaf(v010,  a01 * wfz, v);
                    v = fmaf(v011,  a01 * wcz, v);
                    v = fmaf(v100,  a10 * wfz, v);
                    v = fmaf(v101,  a10 * wcz, v);
                    v = fmaf(v110,  a11 * wfz, v);
                    v = fmaf(v111,  a11 * wcz, v);
                }
                outp[e << 16] = v;
            }
        }
    } else {
        // ---------------- fallback: direct global gather ----------------
        float fi = (float)i0;
        for (int e = 0; e < TI; e++) {
            const float II = fmaf(T00, fi, IIb);
            const float JJ = fmaf(T10, fi, JJb);
            const float KK = fmaf(T20, fi, KKb);
            fi += 1.0f;

            const bool ok = (II > 0.0f) & (JJ > 0.0f) & (KK > 0.0f) &
                            (II <= 255.0f) & (JJ <= 255.0f) & (KK <= 255.0f);
            float v = 0.0f;
            if (ok) {
                const int x0 = __float2int_rd(II);
                const int y0 = __float2int_rd(JJ);
                const int z0 = __float2int_rd(KK);
                const float wcx = II - (float)x0, wfx = 1.0f - wcx;
                const float wcy = JJ - (float)y0, wfy = 1.0f - wcy;
                const float wcz = KK - (float)z0, wfz = 1.0f - wcz;

                const int ox = (x0 < 255) ? 65536 : 0;
                const int oy = (y0 < 255) ? 256 : 0;
                const int oz = (z0 < 255) ? 1 : 0;

                const float* p = img + ((x0 << 16) | (y0 << 8) | z0);
                const float v000 = __ldg(p),            v001 = __ldg(p + oz);
                const float v010 = __ldg(p + oy),       v011 = __ldg(p + oy + oz);
                const float v100 = __ldg(p + ox),       v101 = __ldg(p + ox + oz);
                const float v110 = __ldg(p + ox + oy),  v111 = __ldg(p + ox + oy + oz);

                const float a00 = wfx * wfy, a01 = wfx * wcy;
                const float a10 = wcx * wfy, a11 = wcx * wcy;
                v =      v000 * (a00 * wfz);
                v = fmaf(v001,  a00 * wcz, v);
                v = fmaf(v010,  a01 * wfz, v);
                v = fmaf(v011,  a01 * wcz, v);
                v = fmaf(v100,  a10 * wfz, v);
                v = fmaf(v101,  a10 * wcz, v);
                v = fmaf(v110,  a11 * wfz, v);
                v = fmaf(v111,  a11 * wcz, v);
            }
            outp[e << 16] = v;
        }
    }
}

extern "C" void kernel_launch(void* const* d_in, const int* in_sizes, int n_in,
                              void* d_out, int out_size) {
    const float* img         = (const float*)d_in[0];
    const float* rotation    = (const float*)d_in[1];
    const float* translation = (const float*)d_in[2];
    const float* ref_v2r     = (const float*)d_in[3];
    const float* flo_v2r     = (const float*)d_in[4];
    float* out = (float*)d_out;

    setup_transform_kernel<<<1, 1>>>(rotation, translation, ref_v2r, flo_v2r);
    tiled_trilinear_kernel<<<4096, NTHREADS>>>(img, out);
}

// round 7
// speedup vs baseline: 1.4187x; 1.0232x over previous
#include <cuda_runtime.h>
#include <cstdint>

// ---------------------------------------------------------------------------
// InstanceModelClassic: rigid-transform trilinear resampling of a 256^3 volume
// ---------------------------------------------------------------------------

__device__ float g_T[12];   // 3x4 rows of composed voxel->voxel transform

__device__ static void mat4_inv(const float* A, float* Ainv) {
    float M[4][8];
    for (int r = 0; r < 4; r++) {
        for (int c = 0; c < 4; c++) {
            M[r][c] = A[r * 4 + c];
            M[r][4 + c] = (r == c) ? 1.0f : 0.0f;
        }
    }
    for (int col = 0; col < 4; col++) {
        int piv = col;
        float best = fabsf(M[col][col]);
        for (int r = col + 1; r < 4; r++) {
            float v = fabsf(M[r][col]);
            if (v > best) { best = v; piv = r; }
        }
        if (piv != col)
            for (int c = 0; c < 8; c++) {
                float t = M[col][c]; M[col][c] = M[piv][c]; M[piv][c] = t;
            }
        float inv_p = 1.0f / M[col][col];
        for (int c = 0; c < 8; c++) M[col][c] *= inv_p;
        for (int r = 0; r < 4; r++) {
            if (r == col) continue;
            float f = M[r][col];
            if (f != 0.0f)
                for (int c = 0; c < 8; c++) M[r][c] -= f * M[col][c];
        }
    }
    for (int r = 0; r < 4; r++)
        for (int c = 0; c < 4; c++)
            Ainv[r * 4 + c] = M[r][4 + c];
}

__device__ static void mm4(const float* A, const float* B, float* C) {
    for (int r = 0; r < 4; r++)
        for (int c = 0; c < 4; c++) {
            float s = 0.0f;
            for (int k = 0; k < 4; k++) s += A[r * 4 + k] * B[k * 4 + c];
            C[r * 4 + c] = s;
        }
}

__global__ void setup_transform_kernel(const float* __restrict__ rotation,
                                       const float* __restrict__ translation,
                                       const float* __restrict__ ref_v2r,
                                       const float* __restrict__ flo_v2r) {
    float cx = cosf(rotation[0]), cy = cosf(rotation[1]), cz = cosf(rotation[2]);
    float sx = sinf(rotation[0]), sy = sinf(rotation[1]), sz = sinf(rotation[2]);

    float Rx[9] = {1, 0, 0,   0, cx, -sx,   0, sx, cx};
    float Ry[9] = {cy, 0, sy, 0, 1, 0,      -sy, 0, cy};
    float Rz[9] = {cz, -sz, 0, sz, cz, 0,   0, 0, 1};
    float Ryz[9], R[9];
    for (int r = 0; r < 3; r++)
        for (int c = 0; c < 3; c++) {
            float s = 0.0f;
            for (int k = 0; k < 3; k++) s += Ry[r * 3 + k] * Rz[k * 3 + c];
            Ryz[r * 3 + c] = s;
        }
    for (int r = 0; r < 3; r++)
        for (int c = 0; c < 3; c++) {
            float s = 0.0f;
            for (int k = 0; k < 3; k++) s += Rx[r * 3 + k] * Ryz[k * 3 + c];
            R[r * 3 + c] = s;
        }

    float Trig[16];
    for (int r = 0; r < 3; r++) {
        for (int c = 0; c < 3; c++) Trig[r * 4 + c] = R[r * 3 + c];
        Trig[r * 4 + 3] = translation[r];
    }
    Trig[12] = 0.0f; Trig[13] = 0.0f; Trig[14] = 0.0f; Trig[15] = 1.0f;

    float Finv[16], tmp[16], T[16];
    mat4_inv(flo_v2r, Finv);
    mm4(Trig, ref_v2r, tmp);
    mm4(Finv, tmp, T);

    for (int i = 0; i < 12; i++) g_T[i] = T[i];
}

// ----------------------------------------------------------------------------
// Tiled resample kernel.
//   Output tile: TI x TJ x TK = 8 x 16 x 32  (4096 voxels, 4096 blocks)
//   Input staged: SMX x SMY x SMZ = 14 x 22 x 40 floats = 49280 B
//   512 threads, 3 CTAs/SM (reg ceiling ~42 -> no spills), 48 warps/SM.
// ----------------------------------------------------------------------------
constexpr int TI = 8, TJ = 16, TK = 32;
constexpr int SMX = 14, SMY = 22, SMZ = 40;
constexpr int SM_ELEMS = SMX * SMY * SMZ;        // 12320
constexpr int NTHREADS = 512;
constexpr int PXY = SMY * SMZ;                   // 880 (x pitch, floats)
constexpr int OY = SMZ;                          // 40
constexpr int OX = PXY;                          // 880

__device__ __forceinline__ float axis_min(float t, int lo, int len) {
    return (t >= 0.0f) ? t * (float)lo : t * (float)(lo + len - 1);
}
__device__ __forceinline__ float axis_max(float t, int lo, int len) {
    return (t >= 0.0f) ? t * (float)(lo + len - 1) : t * (float)lo;
}

__device__ __forceinline__ void cp_async16(unsigned int smem_dst, const void* gsrc) {
    asm volatile("cp.async.cg.shared.global [%0], [%1], 16;\n"
                 :: "r"(smem_dst), "l"(gsrc) : "memory");
}
__device__ __forceinline__ void cp_async_wait_all() {
    asm volatile("cp.async.commit_group;\ncp.async.wait_group 0;\n" ::: "memory");
}

__global__ void __launch_bounds__(NTHREADS, 3)
tiled_trilinear_kernel(const float* __restrict__ img, float* __restrict__ out) {
    __shared__ float tile[SM_ELEMS];

    const int bid = blockIdx.x;
    const int k0 = (bid & 7) << 5;           // 8 k-tiles of 32
    const int j0 = ((bid >> 3) & 15) << 4;   // 16 j-tiles of 16
    const int i0 = (bid >> 7) << 3;          // 32 i-tiles of 8

    const float T00 = g_T[0], T01 = g_T[1],  T02 = g_T[2],  T03 = g_T[3];
    const float T10 = g_T[4], T11 = g_T[5],  T12 = g_T[6],  T13 = g_T[7];
    const float T20 = g_T[8], T21 = g_T[9],  T22 = g_T[10], T23 = g_T[11];

    // Input-space bbox of this output tile (block-uniform).
    const float mnI = T03 + axis_min(T00, i0, TI) + axis_min(T01, j0, TJ) + axis_min(T02, k0, TK);
    const float mxI = T03 + axis_max(T00, i0, TI) + axis_max(T01, j0, TJ) + axis_max(T02, k0, TK);
    const float mnJ = T13 + axis_min(T10, i0, TI) + axis_min(T11, j0, TJ) + axis_min(T12, k0, TK);
    const float mxJ = T13 + axis_max(T10, i0, TI) + axis_max(T11, j0, TJ) + axis_max(T12, k0, TK);
    const float mnK = T23 + axis_min(T20, i0, TI) + axis_min(T21, j0, TJ) + axis_min(T22, k0, TK);
    const float mxK = T23 + axis_max(T20, i0, TI) + axis_max(T21, j0, TJ) + axis_max(T22, k0, TK);

    const int loX  = max(__float2int_rd(mnI), 0);
    const int loY  = max(__float2int_rd(mnJ), 0);
    const int loZ  = max(__float2int_rd(mnK), 0);
    const int zloA = loZ & ~3;                       // 16B-aligned z origin
    const int hiX  = min(__float2int_rd(mxI) + 1, 255);
    const int hiY  = min(__float2int_rd(mxJ) + 1, 255);
    const int hiZ  = min(__float2int_rd(mxK) + 1, 255);

    const bool fits = (hiX - loX < SMX) && (hiY - loY < SMY) && (hiZ - zloA < SMZ);

    const int tid = threadIdx.x;
    const int kl = tid & 31;        // k lane (warp-contiguous)
    const int tg = tid >> 5;        // j row within tile
    const int k = k0 + kl;
    const int j = j0 + tg;
    const float fk = (float)k, fj = (float)j;

    // per-thread (j,k)-dependent bases: II = fmaf(T00, fi, IIb)
    const float IIb = fmaf(T01, fj, fmaf(T02, fk, T03));
    const float JJb = fmaf(T11, fj, fmaf(T12, fk, T13));
    const float KKb = fmaf(T21, fj, fmaf(T22, fk, T23));

    float* outp = out + (((i0 << 8) | j) << 8 | k);

    if (fits) {
        // ------------------- stage input region into smem -------------------
        if (zloA + SMZ <= 256) {
            // fully in-range z: cp.async 16B per element
            constexpr int NQ = SMZ / 4;                 // 10
            constexpr int N4 = SMX * SMY * NQ;          // 3080
            const unsigned int smem_base_u32 =
                (unsigned int)__cvta_generic_to_shared(&tile[0]);
            for (int idx = tid; idx < N4; idx += NTHREADS) {
                const int xp = idx / (SMY * NQ);
                const int rem = idx - xp * (SMY * NQ);
                const int yp = rem / NQ;
                const int q = rem - yp * NQ;
                const int xg = min(loX + xp, 255);
                const int yg = min(loY + yp, 255);
                const float* gsrc = img + ((xg << 16) | (yg << 8)) + zloA + (q << 2);
                cp_async16(smem_base_u32 + (((xp * SMY + yp) * SMZ + (q << 2)) << 2), gsrc);
            }
            cp_async_wait_all();
        } else {
            // z clamp needed near the high boundary: scalar staging
            for (int idx = tid; idx < SM_ELEMS; idx += NTHREADS) {
                const int xp = idx / PXY;
                const int rem = idx - xp * PXY;
                const int yp = rem / SMZ;
                const int zp = rem - yp * SMZ;
                const int xg = min(loX + xp, 255);
                const int yg = min(loY + yp, 255);
                const int zg = min(zloA + zp, 255);
                tile[idx] = __ldg(img + ((xg << 16) | (yg << 8) | zg));
            }
        }
        __syncthreads();

        // tile-space offset: base = x0*880 + y0*40 + z0 + Coff
        const int Coff = -(loX * PXY + loY * SMZ + zloA);
        const float* tilep = tile;

        // block-uniform interior test (all voxels strictly inside volume)
        const bool interior = (mnI > 0.01f) && (mxI < 254.99f) &&
                              (mnJ > 0.01f) && (mxJ < 254.99f) &&
                              (mnK > 0.01f) && (mxK < 254.99f);

        if (interior) {
            float fi = (float)i0;
#pragma unroll
            for (int e = 0; e < TI; e++) {
                const float II = fmaf(T00, fi, IIb);
                const float JJ = fmaf(T10, fi, JJb);
                const float KK = fmaf(T20, fi, KKb);
                fi += 1.0f;

                const float fx = floorf(II);
                const float fy = floorf(JJ);
                const float fz = floorf(KK);
                const float wcx = II - fx, wfx = 1.0f - wcx;
                const float wcy = JJ - fy, wfy = 1.0f - wcy;
                const float wcz = KK - fz, wfz = 1.0f - wcz;

                // linear smem index computed in float (exact below 2^24)
                const int base = __float2int_rn(
                    fmaf(fx, (float)PXY, fmaf(fy, (float)SMZ, fz))) + Coff;
                const float* p = tilep + base;

                const float v000 = p[0],        v001 = p[1];
                const float v010 = p[OY],       v011 = p[OY + 1];
                const float v100 = p[OX],       v101 = p[OX + 1];
                const float v110 = p[OX + OY],  v111 = p[OX + OY + 1];

                const float a00 = wfx * wfy, a01 = wfx * wcy;
                const float a10 = wcx * wfy, a11 = wcx * wcy;
                float v;
                v =      v000 * (a00 * wfz);
                v = fmaf(v001,  a00 * wcz, v);
                v = fmaf(v010,  a01 * wfz, v);
                v = fmaf(v011,  a01 * wcz, v);
                v = fmaf(v100,  a10 * wfz, v);
                v = fmaf(v101,  a10 * wcz, v);
                v = fmaf(v110,  a11 * wfz, v);
                v = fmaf(v111,  a11 * wcz, v);

                outp[e << 16] = v;
            }
        } else {
            // boundary tile: per-voxel mask + clamped +1 offsets
            float fi = (float)i0;
#pragma unroll 2
            for (int e = 0; e < TI; e++) {
                const float II = fmaf(T00, fi, IIb);
                const float JJ = fmaf(T10, fi, JJb);
                const float KK = fmaf(T20, fi, KKb);
                fi += 1.0f;

                const bool ok = (II > 0.0f) & (JJ > 0.0f) & (KK > 0.0f) &
                                (II <= 255.0f) & (JJ <= 255.0f) & (KK <= 255.0f);
                float v = 0.0f;
                if (ok) {
                    const int x0 = __float2int_rd(II);
                    const int y0 = __float2int_rd(JJ);
                    const int z0 = __float2int_rd(KK);
                    const float wcx = II - (float)x0, wfx = 1.0f - wcx;
                    const float wcy = JJ - (float)y0, wfy = 1.0f - wcy;
                    const float wcz = KK - (float)z0, wfz = 1.0f - wcz;

                    const int ox = (x0 < 255) ? OX : 0;
                    const int oy = (y0 < 255) ? OY : 0;
                    const int oz = (z0 < 255) ? 1 : 0;

                    const int base = x0 * PXY + y0 * SMZ + z0 + Coff;
                    const float* p = tilep + base;

                    const float v000 = p[0],        v001 = p[oz];
                    const float v010 = p[oy],       v011 = p[oy + oz];
                    const float v100 = p[ox],       v101 = p[ox + oz];
                    const float v110 = p[ox + oy],  v111 = p[ox + oy + oz];

                    const float a00 = wfx * wfy, a01 = wfx * wcy;
                    const float a10 = wcx * wfy, a11 = wcx * wcy;
                    v =      v000 * (a00 * wfz);
                    v = fmaf(v001,  a00 * wcz, v);
                    v = fmaf(v010,  a01 * wfz, v);
                    v = fmaf(v011,  a01 * wcz, v);
                    v = fmaf(v100,  a10 * wfz, v);
                    v = fmaf(v101,  a10 * wcz, v);
                    v = fmaf(v110,  a11 * wfz, v);
                    v = fmaf(v111,  a11 * wcz, v);
                }
                outp[e << 16] = v;
            }
        }
    } else {
        // ---------------- fallback: direct global gather ----------------
        float fi = (float)i0;
        for (int e = 0; e < TI; e++) {
            const float II = fmaf(T00, fi, IIb);
            const float JJ = fmaf(T10, fi, JJb);
            const float KK = fmaf(T20, fi, KKb);
            fi += 1.0f;

            const bool ok = (II > 0.0f) & (JJ > 0.0f) & (KK > 0.0f) &
                            (II <= 255.0f) & (JJ <= 255.0f) & (KK <= 255.0f);
            float v = 0.0f;
            if (ok) {
                const int x0 = __float2int_rd(II);
                const int y0 = __float2int_rd(JJ);
                const int z0 = __float2int_rd(KK);
                const float wcx = II - (float)x0, wfx = 1.0f - wcx;
                const float wcy = JJ - (float)y0, wfy = 1.0f - wcy;
                const float wcz = KK - (float)z0, wfz = 1.0f - wcz;

                const int ox = (x0 < 255) ? 65536 : 0;
                const int oy = (y0 < 255) ? 256 : 0;
                const int oz = (z0 < 255) ? 1 : 0;

                const float* p = img + ((x0 << 16) | (y0 << 8) | z0);
                const float v000 = __ldg(p),            v001 = __ldg(p + oz);
                const float v010 = __ldg(p + oy),       v011 = __ldg(p + oy + oz);
                const float v100 = __ldg(p + ox),       v101 = __ldg(p + ox + oz);
                const float v110 = __ldg(p + ox + oy),  v111 = __ldg(p + ox + oy + oz);

                const float a00 = wfx * wfy, a01 = wfx * wcy;
                const float a10 = wcx * wfy, a11 = wcx * wcy;
                v =      v000 * (a00 * wfz);
                v = fmaf(v001,  a00 * wcz, v);
                v = fmaf(v010,  a01 * wfz, v);
                v = fmaf(v011,  a01 * wcz, v);
                v = fmaf(v100,  a10 * wfz, v);
                v = fmaf(v101,  a10 * wcz, v);
                v = fmaf(v110,  a11 * wfz, v);
                v = fmaf(v111,  a11 * wcz, v);
            }
            outp[e << 16] = v;
        }
    }
}

extern "C" void kernel_launch(void* const* d_in, const int* in_sizes, int n_in,
                              void* d_out, int out_size) {
    const float* img         = (const float*)d_in[0];
    const float* rotation    = (const float*)d_in[1];
    const float* translation = (const float*)d_in[2];
    const float* ref_v2r     = (const float*)d_in[3];
    const float* flo_v2r     = (const float*)d_in[4];
    float* out = (float*)d_out;

    setup_transform_kernel<<<1, 1>>>(rotation, translation, ref_v2r, flo_v2r);
    tiled_trilinear_kernel<<<4096, NTHREADS>>>(img, out);
}

// round 8
// speedup vs baseline: 1.8929x; 1.3343x over previous
#include <cuda_runtime.h>
#include <cstdint>

// ---------------------------------------------------------------------------
// InstanceModelClassic: rigid-transform trilinear resampling of a 256^3 volume
// Tiled smem gather with CONFLICT-FREE pitches (OY, OX multiples of 32 banks).
// ---------------------------------------------------------------------------

__device__ float g_T[12];   // 3x4 rows of composed voxel->voxel transform

__device__ static void mat4_inv(const float* A, float* Ainv) {
    float M[4][8];
    for (int r = 0; r < 4; r++) {
        for (int c = 0; c < 4; c++) {
            M[r][c] = A[r * 4 + c];
            M[r][4 + c] = (r == c) ? 1.0f : 0.0f;
        }
    }
    for (int col = 0; col < 4; col++) {
        int piv = col;
        float best = fabsf(M[col][col]);
        for (int r = col + 1; r < 4; r++) {
            float v = fabsf(M[r][col]);
            if (v > best) { best = v; piv = r; }
        }
        if (piv != col)
            for (int c = 0; c < 8; c++) {
                float t = M[col][c]; M[col][c] = M[piv][c]; M[piv][c] = t;
            }
        float inv_p = 1.0f / M[col][col];
        for (int c = 0; c < 8; c++) M[col][c] *= inv_p;
        for (int r = 0; r < 4; r++) {
            if (r == col) continue;
            float f = M[r][col];
            if (f != 0.0f)
                for (int c = 0; c < 8; c++) M[r][c] -= f * M[col][c];
        }
    }
    for (int r = 0; r < 4; r++)
        for (int c = 0; c < 4; c++)
            Ainv[r * 4 + c] = M[r][4 + c];
}

__device__ static void mm4(const float* A, const float* B, float* C) {
    for (int r = 0; r < 4; r++)
        for (int c = 0; c < 4; c++) {
            float s = 0.0f;
            for (int k = 0; k < 4; k++) s += A[r * 4 + k] * B[k * 4 + c];
            C[r * 4 + c] = s;
        }
}

__global__ void setup_transform_kernel(const float* __restrict__ rotation,
                                       const float* __restrict__ translation,
                                       const float* __restrict__ ref_v2r,
                                       const float* __restrict__ flo_v2r) {
    float cx = cosf(rotation[0]), cy = cosf(rotation[1]), cz = cosf(rotation[2]);
    float sx = sinf(rotation[0]), sy = sinf(rotation[1]), sz = sinf(rotation[2]);

    float Rx[9] = {1, 0, 0,   0, cx, -sx,   0, sx, cx};
    float Ry[9] = {cy, 0, sy, 0, 1, 0,      -sy, 0, cy};
    float Rz[9] = {cz, -sz, 0, sz, cz, 0,   0, 0, 1};
    float Ryz[9], R[9];
    for (int r = 0; r < 3; r++)
        for (int c = 0; c < 3; c++) {
            float s = 0.0f;
            for (int k = 0; k < 3; k++) s += Ry[r * 3 + k] * Rz[k * 3 + c];
            Ryz[r * 3 + c] = s;
        }
    for (int r = 0; r < 3; r++)
        for (int c = 0; c < 3; c++) {
            float s = 0.0f;
            for (int k = 0; k < 3; k++) s += Rx[r * 3 + k] * Ryz[k * 3 + c];
            R[r * 3 + c] = s;
        }

    float Trig[16];
    for (int r = 0; r < 3; r++) {
        for (int c = 0; c < 3; c++) Trig[r * 4 + c] = R[r * 3 + c];
        Trig[r * 4 + 3] = translation[r];
    }
    Trig[12] = 0.0f; Trig[13] = 0.0f; Trig[14] = 0.0f; Trig[15] = 1.0f;

    float Finv[16], tmp[16], T[16];
    mat4_inv(flo_v2r, Finv);
    mm4(Trig, ref_v2r, tmp);
    mm4(Finv, tmp, T);

    for (int i = 0; i < 12; i++) g_T[i] = T[i];
}

// ----------------------------------------------------------------------------
// Tile geometry.
//   Output tile: TI x TJ x TK = 8 x 16 x 32  (4096 voxels, 4096 blocks)
//   Staged region: SMX x SMY rows, each row 44 floats used, PITCHED TO 64.
//   OY = 64  (256 B  == 0 mod 32 banks)  -> y-jump lanes: ZERO bank conflicts
//   OX = 64*21 = 1344 (== 0 mod 32 banks) -> x-jump lanes: ZERO bank conflicts
//   smem = 14*21*64*4 = 75264 B -> 3 CTA/SM (dynamic smem), 48 warps/SM.
// ----------------------------------------------------------------------------
constexpr int TI = 8, TJ = 16, TK = 32;
constexpr int SMX = 14, SMY = 21;
constexpr int OY = 64;                    // z pitch (floats)
constexpr int OX = OY * SMY;              // 1344
constexpr int ZCAP = 44;                  // staged z extent (11 quads)
constexpr int NQ = ZCAP / 4;              // 11
constexpr int SM_FLOATS = SMX * SMY * OY; // 18816
constexpr int SM_BYTES = SM_FLOATS * 4;   // 75264
constexpr int NTHREADS = 512;

__device__ __forceinline__ float axis_min(float t, int lo, int len) {
    return (t >= 0.0f) ? t * (float)lo : t * (float)(lo + len - 1);
}
__device__ __forceinline__ float axis_max(float t, int lo, int len) {
    return (t >= 0.0f) ? t * (float)(lo + len - 1) : t * (float)lo;
}

__device__ __forceinline__ void cp_async16(unsigned int smem_dst, const void* gsrc) {
    asm volatile("cp.async.cg.shared.global [%0], [%1], 16;\n"
                 :: "r"(smem_dst), "l"(gsrc) : "memory");
}
__device__ __forceinline__ void cp_async_wait_all() {
    asm volatile("cp.async.commit_group;\ncp.async.wait_group 0;\n" ::: "memory");
}

__global__ void __launch_bounds__(NTHREADS, 3)
tiled_trilinear_kernel(const float* __restrict__ img, float* __restrict__ out) {
    extern __shared__ float tile[];

    const int bid = blockIdx.x;
    const int k0 = (bid & 7) << 5;           // 8 k-tiles of 32
    const int j0 = ((bid >> 3) & 15) << 4;   // 16 j-tiles of 16
    const int i0 = (bid >> 7) << 3;          // 32 i-tiles of 8

    const float T00 = g_T[0], T01 = g_T[1],  T02 = g_T[2],  T03 = g_T[3];
    const float T10 = g_T[4], T11 = g_T[5],  T12 = g_T[6],  T13 = g_T[7];
    const float T20 = g_T[8], T21 = g_T[9],  T22 = g_T[10], T23 = g_T[11];

    // Input-space bbox of this output tile (block-uniform).
    const float mnI = T03 + axis_min(T00, i0, TI) + axis_min(T01, j0, TJ) + axis_min(T02, k0, TK);
    const float mxI = T03 + axis_max(T00, i0, TI) + axis_max(T01, j0, TJ) + axis_max(T02, k0, TK);
    const float mnJ = T13 + axis_min(T10, i0, TI) + axis_min(T11, j0, TJ) + axis_min(T12, k0, TK);
    const float mxJ = T13 + axis_max(T10, i0, TI) + axis_max(T11, j0, TJ) + axis_max(T12, k0, TK);
    const float mnK = T23 + axis_min(T20, i0, TI) + axis_min(T21, j0, TJ) + axis_min(T22, k0, TK);
    const float mxK = T23 + axis_max(T20, i0, TI) + axis_max(T21, j0, TJ) + axis_max(T22, k0, TK);

    const int loX  = max(__float2int_rd(mnI), 0);
    const int loY  = max(__float2int_rd(mnJ), 0);
    const int loZ  = max(__float2int_rd(mnK), 0);
    const int zloA = loZ & ~3;                       // 16B-aligned z origin
    const int hiX  = min(__float2int_rd(mxI) + 1, 255);
    const int hiY  = min(__float2int_rd(mxJ) + 1, 255);
    const int hiZ  = min(__float2int_rd(mxK) + 1, 255);

    const bool fits = (hiX - loX < SMX) && (hiY - loY < SMY) && (hiZ - zloA < ZCAP);

    const int tid = threadIdx.x;
    const int kl = tid & 31;        // k lane (warp-contiguous)
    const int tg = tid >> 5;        // j row within tile
    const int k = k0 + kl;
    const int j = j0 + tg;
    const float fk = (float)k, fj = (float)j;

    // per-thread (j,k)-dependent bases: II = fmaf(T00, fi, IIb)
    const float IIb = fmaf(T01, fj, fmaf(T02, fk, T03));
    const float JJb = fmaf(T11, fj, fmaf(T12, fk, T13));
    const float KKb = fmaf(T21, fj, fmaf(T22, fk, T23));

    float* outp = out + (((i0 << 8) | j) << 8 | k);

    if (fits) {
        // ---- stage: always vectorized; clamped sources for never-read slots ----
        // 294 rows x 11 quads = 3234 cp.async of 16B. Row pitch 256B (16B-aligned).
        {
            const unsigned int smem_u32 =
                (unsigned int)__cvta_generic_to_shared(&tile[0]);
            constexpr int NQUADS = SMX * SMY * NQ;   // 3234
            for (int idx = tid; idx < NQUADS; idx += NTHREADS) {
                const int r = idx / NQ;
                const int q = idx - r * NQ;
                const int xp = r / SMY;
                const int yp = r - xp * SMY;
                const int xg = min(loX + xp, 255);
                const int yg = min(loY + yp, 255);
                const int zg = min(zloA + (q << 2), 252);   // clamp: slots past 255 never read
                const float* gsrc = img + ((xg << 16) | (yg << 8) | zg);
                cp_async16(smem_u32 + (((r << 6) + (q << 2)) << 2), gsrc);
            }
            cp_async_wait_all();
        }
        __syncthreads();

        // tile-space: index = (x0-loX)*OX + (y0-loY)*OY + (z0-zloA)
        const int Coff = -(loX * OX + loY * OY + zloA);
        const float* tilep = tile;

        const bool interior = (mnI > 0.01f) && (mxI < 254.99f) &&
                              (mnJ > 0.01f) && (mxJ < 254.99f) &&
                              (mnK > 0.01f) && (mxK < 254.99f);

        if (interior) {
            float fi = (float)i0;
#pragma unroll
            for (int e = 0; e < TI; e++) {
                const float II = fmaf(T00, fi, IIb);
                const float JJ = fmaf(T10, fi, JJb);
                const float KK = fmaf(T20, fi, KKb);
                fi += 1.0f;

                const float fx = floorf(II);
                const float fy = floorf(JJ);
                const float fz = floorf(KK);
                const float wcx = II - fx, wfx = 1.0f - wcx;
                const float wcy = JJ - fy, wfy = 1.0f - wcy;
                const float wcz = KK - fz, wfz = 1.0f - wcz;

                // exact float index (max 14*1344+20*64+43 < 2^24)
                const int base = __float2int_rn(
                    fmaf(fx, (float)OX, fmaf(fy, (float)OY, fz))) + Coff;
                const float* p = tilep + base;

                const float v000 = p[0],        v001 = p[1];
                const float v010 = p[OY],       v011 = p[OY + 1];
                const float v100 = p[OX],       v101 = p[OX + 1];
                const float v110 = p[OX + OY],  v111 = p[OX + OY + 1];

                const float a00 = wfx * wfy, a01 = wfx * wcy;
                const float a10 = wcx * wfy, a11 = wcx * wcy;
                float v;
                v =      v000 * (a00 * wfz);
                v = fmaf(v001,  a00 * wcz, v);
                v = fmaf(v010,  a01 * wfz, v);
                v = fmaf(v011,  a01 * wcz, v);
                v = fmaf(v100,  a10 * wfz, v);
                v = fmaf(v101,  a10 * wcz, v);
                v = fmaf(v110,  a11 * wfz, v);
                v = fmaf(v111,  a11 * wcz, v);

                outp[e << 16] = v;
            }
        } else {
            // boundary tile: per-voxel mask + clamped +1 offsets
            float fi = (float)i0;
#pragma unroll 2
            for (int e = 0; e < TI; e++) {
                const float II = fmaf(T00, fi, IIb);
                const float JJ = fmaf(T10, fi, JJb);
                const float KK = fmaf(T20, fi, KKb);
                fi += 1.0f;

                const bool ok = (II > 0.0f) & (JJ > 0.0f) & (KK > 0.0f) &
                                (II <= 255.0f) & (JJ <= 255.0f) & (KK <= 255.0f);
                float v = 0.0f;
                if (ok) {
                    const int x0 = __float2int_rd(II);
                    const int y0 = __float2int_rd(JJ);
                    const int z0 = __float2int_rd(KK);
                    const float wcx = II - (float)x0, wfx = 1.0f - wcx;
                    const float wcy = JJ - (float)y0, wfy = 1.0f - wcy;
                    const float wcz = KK - (float)z0, wfz = 1.0f - wcz;

                    const int ox = (x0 < 255) ? OX : 0;
                    const int oy = (y0 < 255) ? OY : 0;
                    const int oz = (z0 < 255) ? 1 : 0;

                    const int base = x0 * OX + y0 * OY + z0 + Coff;
                    const float* p = tilep + base;

                    const float v000 = p[0],        v001 = p[oz];
                    const float v010 = p[oy],       v011 = p[oy + oz];
                    const float v100 = p[ox],       v101 = p[ox + oz];
                    const float v110 = p[ox + oy],  v111 = p[ox + oy + oz];

                    const float a00 = wfx * wfy, a01 = wfx * wcy;
                    const float a10 = wcx * wfy, a11 = wcx * wcy;
                    v =      v000 * (a00 * wfz);
                    v = fmaf(v001,  a00 * wcz, v);
                    v = fmaf(v010,  a01 * wfz, v);
                    v = fmaf(v011,  a01 * wcz, v);
                    v = fmaf(v100,  a10 * wfz, v);
                    v = fmaf(v101,  a10 * wcz, v);
                    v = fmaf(v110,  a11 * wfz, v);
                    v = fmaf(v111,  a11 * wcz, v);
                }
                outp[e << 16] = v;
            }
        }
    } else {
        // ---------------- fallback: direct global gather ----------------
        float fi = (float)i0;
        for (int e = 0; e < TI; e++) {
            const float II = fmaf(T00, fi, IIb);
            const float JJ = fmaf(T10, fi, JJb);
            const float KK = fmaf(T20, fi, KKb);
            fi += 1.0f;

            const bool ok = (II > 0.0f) & (JJ > 0.0f) & (KK > 0.0f) &
                            (II <= 255.0f) & (JJ <= 255.0f) & (KK <= 255.0f);
            float v = 0.0f;
            if (ok) {
                const int x0 = __float2int_rd(II);
                const int y0 = __float2int_rd(JJ);
                const int z0 = __float2int_rd(KK);
                const float wcx = II - (float)x0, wfx = 1.0f - wcx;
                const float wcy = JJ - (float)y0, wfy = 1.0f - wcy;
                const float wcz = KK - (float)z0, wfz = 1.0f - wcz;

                const int ox = (x0 < 255) ? 65536 : 0;
                const int oy = (y0 < 255) ? 256 : 0;
                const int oz = (z0 < 255) ? 1 : 0;

                const float* p = img + ((x0 << 16) | (y0 << 8) | z0);
                const float v000 = __ldg(p),            v001 = __ldg(p + oz);
                const float v010 = __ldg(p + oy),       v011 = __ldg(p + oy + oz);
                const float v100 = __ldg(p + ox),       v101 = __ldg(p + ox + oz);
                const float v110 = __ldg(p + ox + oy),  v111 = __ldg(p + ox + oy + oz);

                const float a00 = wfx * wfy, a01 = wfx * wcy;
                const float a10 = wcx * wfy, a11 = wcx * wcy;
                v =      v000 * (a00 * wfz);
                v = fmaf(v001,  a00 * wcz, v);
                v = fmaf(v010,  a01 * wfz, v);
                v = fmaf(v011,  a01 * wcz, v);
                v = fmaf(v100,  a10 * wfz, v);
                v = fmaf(v101,  a10 * wcz, v);
                v = fmaf(v110,  a11 * wfz, v);
                v = fmaf(v111,  a11 * wcz, v);
            }
            outp[e << 16] = v;
        }
    }
}

extern "C" void kernel_launch(void* const* d_in, const int* in_sizes, int n_in,
                              void* d_out, int out_size) {
    const float* img         = (const float*)d_in[0];
    const float* rotation    = (const float*)d_in[1];
    const float* translation = (const float*)d_in[2];
    const float* ref_v2r     = (const float*)d_in[3];
    const float* flo_v2r     = (const float*)d_in[4];
    float* out = (float*)d_out;

    setup_transform_kernel<<<1, 1>>>(rotation, translation, ref_v2r, flo_v2r);

    static bool attr_set = false;
    if (!attr_set) {
        cudaFuncSetAttribute(tiled_trilinear_kernel,
                             cudaFuncAttributeMaxDynamicSharedMemorySize, SM_BYTES);
        attr_set = true;
    }

    tiled_trilinear_kernel<<<4096, NTHREADS, SM_BYTES>>>(img, out);
}